// round 9
// baseline (speedup 1.0000x reference)
#include <cuda_runtime.h>
#include <cstdint>

// Flow1 via mma.sync m16n8k16 bf16 (3-product compensation), packed pre-split
// weights, m32-per-warp tiling, cp.async double-buffered weight staging.
// B=262144 rows, Z=128, ZH=64, HS=50 (padded 56), 4 couplings.
// Out: [ z (B*128) | logpz (B) | logqz (B) ] fp32.
//
// CTA = 128 rows, 256 thr = 8 warps = 4 m-groups(32 rows) x 2 n-halves.
// 1 CTA/SM, ~216 KB smem: weights double-buffered via cp.async.

#define ZZ 128
#define ZH 64
#define HS 50
#define NC 4
#define TPB 256
#define MR 128
#define PZ 68      // fp32 z pitch (floats)
#define KPI 36     // k-pair pitch (words)

// packed-weight word offsets (within one buffer)
#define W0H 0                  // 56 n x 36 kp
#define W0L 2016
#define W1H 4032               // 64 n x 36 kp
#define W1L 6336
#define W2H 8640
#define W2L 10944
#define WTOT 13248             // words = 52992 B

// smem word offsets
#define OW0  0
#define OW1  13248
#define OZ1  26496             // 128 x 68 fp32
#define OZ2  35200
#define OHH  43904             // 128 x 36 packed
#define OHL  48512
#define OB   53120             // 2 buffers x 192
#define OQ0  53504             // 128
#define OLD  53632             // 2*128
#define OSS  53888             // 2*128
#define SMEM_WORDS 54144
#define SMEM_BYTES (SMEM_WORDS * 4)    // 216576

__device__ __align__(16) unsigned gW[NC][WTOT];
__device__ __align__(16) float gBB[NC][192];

__device__ __forceinline__ float tanh_fast(float x) {
    float r;
    asm("tanh.approx.f32 %0, %1;" : "=f"(r) : "f"(x));
    return r;
}
__device__ __forceinline__ unsigned pack2(float hi_elem, float lo_elem) {
    unsigned r;
    asm("cvt.rn.bf16x2.f32 %0, %1, %2;" : "=r"(r) : "f"(hi_elem), "f"(lo_elem));
    return r;
}
// split (x = even-k, y = odd-k) into packed hi word + packed lo word
__device__ __forceinline__ void split2(float x, float y, unsigned& h, unsigned& l) {
    h = pack2(y, x);
    float hx = __uint_as_float(h << 16);
    float hy = __uint_as_float(h & 0xFFFF0000u);
    l = pack2(y - hy, x - hx);
}
__device__ __forceinline__ void mma16(float (&d)[4], const unsigned* a,
                                      unsigned b0, unsigned b1) {
    asm volatile(
        "mma.sync.aligned.m16n8k16.row.col.f32.bf16.bf16.f32 "
        "{%0,%1,%2,%3}, {%4,%5,%6,%7}, {%8,%9}, {%0,%1,%2,%3};"
        : "+f"(d[0]), "+f"(d[1]), "+f"(d[2]), "+f"(d[3])
        : "r"(a[0]), "r"(a[1]), "r"(a[2]), "r"(a[3]), "r"(b0), "r"(b1));
}
__device__ __forceinline__ void cp16(void* sdst, const void* gsrc) {
    unsigned s = (unsigned)__cvta_generic_to_shared(sdst);
    asm volatile("cp.async.cg.shared.global [%0], [%1], 16;" :: "r"(s), "l"(gsrc));
}
#define CP_COMMIT() asm volatile("cp.async.commit_group;" ::: "memory")
#define CP_WAIT0()  asm volatile("cp.async.wait_group 0;" ::: "memory")

// ---------------- pre-split kernel ----------------
__global__ void presplit_kernel(const float* __restrict__ W_in,  const float* __restrict__ b_in,
                                const float* __restrict__ W_mu,  const float* __restrict__ b_mu,
                                const float* __restrict__ W_sig, const float* __restrict__ b_sig)
{
    const int cc = blockIdx.x;
    const int tid = threadIdx.x;
    for (int idx = tid; idx < 56 * KPI; idx += blockDim.x) {
        int n = idx / KPI, kp = idx - n * KPI;
        int k0 = 2 * kp, k1 = k0 + 1;
        float v0 = (n < HS && k0 < ZH) ? W_in[cc * HS * ZH + n * ZH + k0] : 0.0f;
        float v1 = (n < HS && k1 < ZH) ? W_in[cc * HS * ZH + n * ZH + k1] : 0.0f;
        unsigned h, l;
        split2(v0, v1, h, l);
        gW[cc][W0H + idx] = h;
        gW[cc][W0L + idx] = l;
    }
    for (int idx = tid; idx < 64 * KPI; idx += blockDim.x) {
        int n = idx / KPI, kp = idx - n * KPI;
        int k0 = 2 * kp, k1 = k0 + 1;
        float m0 = (k0 < HS) ? W_mu [cc * ZH * HS + n * HS + k0] : 0.0f;
        float m1 = (k1 < HS) ? W_mu [cc * ZH * HS + n * HS + k1] : 0.0f;
        float s0 = (k0 < HS) ? W_sig[cc * ZH * HS + n * HS + k0] : 0.0f;
        float s1 = (k1 < HS) ? W_sig[cc * ZH * HS + n * HS + k1] : 0.0f;
        unsigned h, l;
        split2(m0, m1, h, l);
        gW[cc][W1H + idx] = h;
        gW[cc][W1L + idx] = l;
        split2(s0, s1, h, l);
        gW[cc][W2H + idx] = h;
        gW[cc][W2L + idx] = l;
    }
    if (tid < 64) {
        gBB[cc][tid]       = (tid < HS) ? b_in[cc * HS + tid] : 0.0f;
        gBB[cc][64 + tid]  = b_mu [cc * ZH + tid];
        gBB[cc][128 + tid] = b_sig[cc * ZH + tid];
    }
}

// ---------------- main kernel ----------------
__global__ void __launch_bounds__(TPB, 1)
flow_kernel(const float* __restrict__ mean,  const float* __restrict__ logvar,
            const float* __restrict__ eps,
            float* __restrict__ out, int Brows)
{
    extern __shared__ float sm[];
    float*    sZ1 = sm + OZ1;
    float*    sZ2 = sm + OZ2;
    unsigned* uHH = (unsigned*)(sm + OHH);
    unsigned* uHL = (unsigned*)(sm + OHL);
    float*    sQ0 = sm + OQ0;
    float*    sLD = sm + OLD;
    float*    sSS = sm + OSS;

    const int tid  = threadIdx.x;
    const int lane = tid & 31;
    const int wid  = tid >> 5;
    const int wm   = wid & 3;          // m-group: rows 32*wm..+31
    const int wn   = wid >> 2;         // n-half
    const int gid  = lane >> 2;
    const int tig  = lane & 3;
    const int rb   = 32 * wm;
    const int rowBase = blockIdx.x * MR;

    // ---- prefetch coupling 0 weights+biases (overlaps reparam) ----
    {
        const float4* srcW = (const float4*)(&gW[0][0]);
        float4* dstW = (float4*)(sm + OW0);
        for (int i = tid; i < WTOT / 4; i += TPB) cp16(dstW + i, srcW + i);
        if (tid < 48) cp16((float4*)(sm + OB) + tid, (const float4*)(&gBB[0][0]) + tid);
        CP_COMMIT();
    }

    // ---- zero H k-pad (kp 28..31, all rows) ----
    for (int i = tid; i < 512; i += TPB) {
        int r = i >> 2, kp = 28 + (i & 3);
        uHH[r * KPI + kp] = 0u;
        uHL[r * KPI + kp] = 0u;
    }

    // ================= reparam (2 threads/row) =================
    {
        const int rrow = tid >> 1, p = tid & 1;
        float part = 0.0f;
#pragma unroll
        for (int j = 0; j < 16; j++) {
            int q = p + 2 * j;
            size_t g = (size_t)(rowBase + rrow) * 32 + q;
            float4 mv = ((const float4*)mean  )[g];
            float4 lv = ((const float4*)logvar)[g];
            float4 ev = ((const float4*)eps   )[g];
            float4 z4;
            z4.x = fmaf(ev.x, __expf(0.5f * lv.x), mv.x);
            z4.y = fmaf(ev.y, __expf(0.5f * lv.y), mv.y);
            z4.z = fmaf(ev.z, __expf(0.5f * lv.z), mv.z);
            z4.w = fmaf(ev.w, __expf(0.5f * lv.w), mv.w);
            part += lv.x + lv.y + lv.z + lv.w;
            part = fmaf(ev.x, ev.x, part);
            part = fmaf(ev.y, ev.y, part);
            part = fmaf(ev.z, ev.z, part);
            part = fmaf(ev.w, ev.w, part);
            if (q < 16)
                *(float4*)&sZ1[rrow * PZ + 4 * q] = z4;
            else
                *(float4*)&sZ2[rrow * PZ + 4 * (q - 16)] = z4;
        }
        part += __shfl_xor_sync(0xffffffffu, part, 1);
        if (p == 0) sQ0[rrow] = -0.5f * part;
    }

    float ldp[4] = {0.f, 0.f, 0.f, 0.f};
    float ssp[4] = {0.f, 0.f, 0.f, 0.f};

    // ================= couplings =================
#pragma unroll 1
    for (int cc = 0; cc < NC; cc++) {
        CP_WAIT0();
        __syncthreads();               // weights(cc) + z/H buffers ready

        // prefetch next coupling into the other buffer
        if (cc < 3) {
            int nb = (cc + 1) & 1;
            const float4* srcW = (const float4*)(&gW[cc + 1][0]);
            float4* dstW = (float4*)(sm + (nb ? OW1 : OW0));
            for (int i = tid; i < WTOT / 4; i += TPB) cp16(dstW + i, srcW + i);
            if (tid < 48)
                cp16((float4*)(sm + OB + 192 * nb) + tid,
                     (const float4*)(&gBB[cc + 1][0]) + tid);
            CP_COMMIT();
        }

        unsigned* uW  = (unsigned*)(sm + ((cc & 1) ? OW1 : OW0));
        const float* sB0 = sm + OB + 192 * (cc & 1);
        const float* sB1 = sB0 + 64;
        const float* sB2 = sB0 + 128;
        const float* sZa = (cc & 1) ? sZ2 : sZ1;
        float*       sZu = (cc & 1) ? sZ1 : sZ2;

        // ---- GEMM1: H = tanh(Za @ W0^T + b0); m32 x n(56, split 4/3) ----
        {
            const int NT = wn ? 3 : 4;
            float acc[2][4][4] = {};
#pragma unroll
            for (int c = 0; c < 4; c++) {
                unsigned ah[2][4], al[2][4];
#pragma unroll
                for (int s2 = 0; s2 < 2; s2++) {
                    int ra0 = rb + 16 * s2 + gid, ra1 = ra0 + 8;
                    float2 v00 = ((const float2*)&sZa[ra0 * PZ])[tig +     8 * c];
                    float2 v10 = ((const float2*)&sZa[ra1 * PZ])[tig +     8 * c];
                    float2 v01 = ((const float2*)&sZa[ra0 * PZ])[tig + 4 + 8 * c];
                    float2 v11 = ((const float2*)&sZa[ra1 * PZ])[tig + 4 + 8 * c];
                    split2(v00.x, v00.y, ah[s2][0], al[s2][0]);
                    split2(v10.x, v10.y, ah[s2][1], al[s2][1]);
                    split2(v01.x, v01.y, ah[s2][2], al[s2][2]);
                    split2(v11.x, v11.y, ah[s2][3], al[s2][3]);
                }
#pragma unroll
                for (int nn = 0; nn < 4; nn++) {
                    if (nn >= NT) break;
                    int nrow = 8 * (wn * 4 + nn) + gid;
                    unsigned bh0 = uW[W0H + nrow * KPI + tig +     8 * c];
                    unsigned bh1 = uW[W0H + nrow * KPI + tig + 4 + 8 * c];
                    unsigned bl0 = uW[W0L + nrow * KPI + tig +     8 * c];
                    unsigned bl1 = uW[W0L + nrow * KPI + tig + 4 + 8 * c];
#pragma unroll
                    for (int s2 = 0; s2 < 2; s2++) {
                        mma16(acc[s2][nn], ah[s2], bh0, bh1);
                        mma16(acc[s2][nn], ah[s2], bl0, bl1);
                        mma16(acc[s2][nn], al[s2], bh0, bh1);
                    }
                }
            }
            // epilogue: bias + tanh, write H pre-split/packed
#pragma unroll
            for (int nn = 0; nn < 4; nn++) {
                if (nn >= NT) break;
                int nt  = wn * 4 + nn;
                int col = 8 * nt + 2 * tig;
                int kp  = 4 * nt + tig;
                float bb0 = sB0[col], bb1 = sB0[col + 1];
#pragma unroll
                for (int s2 = 0; s2 < 2; s2++) {
                    int ra0 = rb + 16 * s2 + gid, ra1 = ra0 + 8;
                    float t00 = tanh_fast(acc[s2][nn][0] + bb0);
                    float t01 = tanh_fast(acc[s2][nn][1] + bb1);
                    float t10 = tanh_fast(acc[s2][nn][2] + bb0);
                    float t11 = tanh_fast(acc[s2][nn][3] + bb1);
                    unsigned h, l;
                    split2(t00, t01, h, l);
                    uHH[ra0 * KPI + kp] = h;
                    uHL[ra0 * KPI + kp] = l;
                    split2(t10, t11, h, l);
                    uHH[ra1 * KPI + kp] = h;
                    uHL[ra1 * KPI + kp] = l;
                }
            }
        }
        __syncthreads();

        // ---- GEMM2: mu/sig heads; m32 x n32 (4 tiles), K=64 ----
        {
            float am [2][4][4] = {};
            float as2[2][4][4] = {};
#pragma unroll
            for (int c = 0; c < 4; c++) {
                unsigned ah[2][4], al[2][4];
#pragma unroll
                for (int s2 = 0; s2 < 2; s2++) {
                    int ra0 = rb + 16 * s2 + gid, ra1 = ra0 + 8;
                    ah[s2][0] = uHH[ra0 * KPI + tig +     8 * c];
                    ah[s2][1] = uHH[ra1 * KPI + tig +     8 * c];
                    ah[s2][2] = uHH[ra0 * KPI + tig + 4 + 8 * c];
                    ah[s2][3] = uHH[ra1 * KPI + tig + 4 + 8 * c];
                    al[s2][0] = uHL[ra0 * KPI + tig +     8 * c];
                    al[s2][1] = uHL[ra1 * KPI + tig +     8 * c];
                    al[s2][2] = uHL[ra0 * KPI + tig + 4 + 8 * c];
                    al[s2][3] = uHL[ra1 * KPI + tig + 4 + 8 * c];
                }
#pragma unroll
                for (int nn = 0; nn < 4; nn++) {
                    int nrow = 8 * (wn * 4 + nn) + gid;
                    unsigned bh0 = uW[W1H + nrow * KPI + tig +     8 * c];
                    unsigned bh1 = uW[W1H + nrow * KPI + tig + 4 + 8 * c];
                    unsigned bl0 = uW[W1L + nrow * KPI + tig +     8 * c];
                    unsigned bl1 = uW[W1L + nrow * KPI + tig + 4 + 8 * c];
#pragma unroll
                    for (int s2 = 0; s2 < 2; s2++) {
                        mma16(am[s2][nn], ah[s2], bh0, bh1);
                        mma16(am[s2][nn], ah[s2], bl0, bl1);
                        mma16(am[s2][nn], al[s2], bh0, bh1);
                    }
                    bh0 = uW[W2H + nrow * KPI + tig +     8 * c];
                    bh1 = uW[W2H + nrow * KPI + tig + 4 + 8 * c];
                    bl0 = uW[W2L + nrow * KPI + tig +     8 * c];
                    bl1 = uW[W2L + nrow * KPI + tig + 4 + 8 * c];
#pragma unroll
                    for (int s2 = 0; s2 < 2; s2++) {
                        mma16(as2[s2][nn], ah[s2], bh0, bh1);
                        mma16(as2[s2][nn], ah[s2], bl0, bl1);
                        mma16(as2[s2][nn], al[s2], bh0, bh1);
                    }
                }
            }
            // ---- epilogue: sig, z update, logdet ----
            const bool fin = (cc >= 2);
#pragma unroll
            for (int s2 = 0; s2 < 2; s2++) {
                int ra0 = rb + 16 * s2 + gid, ra1 = ra0 + 8;
#pragma unroll
                for (int nn = 0; nn < 4; nn++) {
                    int col = 8 * (wn * 4 + nn) + 2 * tig;
#pragma unroll
                    for (int d = 0; d < 2; d++) {
                        float bm = sB1[col + d];
                        float bs = sB2[col + d];
                        {
                            float mu = am[s2][nn][d] + bm;
                            float x  = as2[s2][nn][d] + bs;
                            float sg = fmaf(tanh_fast(0.5f * x), 0.5f, 0.5f);
                            ldp[2 * s2] += __logf(sg);
                            float zn = fmaf(sZu[ra0 * PZ + col + d], sg, mu);
                            sZu[ra0 * PZ + col + d] = zn;
                            if (fin) ssp[2 * s2] = fmaf(zn, zn, ssp[2 * s2]);
                        }
                        {
                            float mu = am[s2][nn][d + 2] + bm;
                            float x  = as2[s2][nn][d + 2] + bs;
                            float sg = fmaf(tanh_fast(0.5f * x), 0.5f, 0.5f);
                            ldp[2 * s2 + 1] += __logf(sg);
                            float zn = fmaf(sZu[ra1 * PZ + col + d], sg, mu);
                            sZu[ra1 * PZ + col + d] = zn;
                            if (fin) ssp[2 * s2 + 1] = fmaf(zn, zn, ssp[2 * s2 + 1]);
                        }
                    }
                }
            }
        }
        __syncthreads();
    }

    // ================= write z (coalesced float4) =================
#pragma unroll
    for (int i = 0; i < 16; i++) {
        int idx = tid + TPB * i;            // 0..4095
        int row = idx >> 5, q = idx & 31;
        float4 v = (q < 16)
            ? *(const float4*)&sZ1[row * PZ + 4 * q]
            : *(const float4*)&sZ2[row * PZ + 4 * (q - 16)];
        ((float4*)out)[(size_t)(rowBase + row) * 32 + q] = v;
    }

    // ================= densities =================
#pragma unroll
    for (int s = 0; s < 4; s++) {
        float l = ldp[s], v = ssp[s];
        l += __shfl_xor_sync(0xffffffffu, l, 1);
        l += __shfl_xor_sync(0xffffffffu, l, 2);
        v += __shfl_xor_sync(0xffffffffu, v, 1);
        v += __shfl_xor_sync(0xffffffffu, v, 2);
        if (tig == 0) {
            int row = rb + 16 * (s >> 1) + 8 * (s & 1) + gid;
            sLD[wn * 128 + row] = l;
            sSS[wn * 128 + row] = v;
        }
    }
    __syncthreads();
    if (tid < 128) {
        float l = sLD[tid] + sLD[128 + tid];
        float s = sSS[tid] + sSS[128 + tid];
        size_t base = (size_t)Brows * ZZ;
        out[base + rowBase + tid]         = -0.5f * s;
        out[base + Brows + rowBase + tid] = sQ0[tid] - l;
    }
}

extern "C" void kernel_launch(void* const* d_in, const int* in_sizes, int n_in,
                              void* d_out, int out_size)
{
    const float* mean   = (const float*)d_in[0];
    const float* logvar = (const float*)d_in[1];
    const float* eps    = (const float*)d_in[2];
    const float* W_in   = (const float*)d_in[3];
    const float* b_in   = (const float*)d_in[4];
    const float* W_mu   = (const float*)d_in[5];
    const float* b_mu   = (const float*)d_in[6];
    const float* W_sig  = (const float*)d_in[7];
    const float* b_sig  = (const float*)d_in[8];
    float* out = (float*)d_out;

    int Brows = in_sizes[0] / ZZ;

    cudaFuncSetAttribute(flow_kernel, cudaFuncAttributeMaxDynamicSharedMemorySize, SMEM_BYTES);

    presplit_kernel<<<NC, 256>>>(W_in, b_in, W_mu, b_mu, W_sig, b_sig);
    flow_kernel<<<Brows / MR, TPB, SMEM_BYTES>>>(mean, logvar, eps, out, Brows);
}

// round 11
// speedup vs baseline: 1.0551x; 1.0551x over previous
#include <cuda_runtime.h>
#include <cstdint>

// Flow1 via mma.sync m16n8k16 bf16 (3-product compensation), packed pre-split
// weights, m32 x n16 warp tiles, 16 warps/CTA, cp.async-hidden weight staging.
// B=262144 rows, Z=128, ZH=64, HS=50 (padded 56), 4 couplings.
// Out: [ z (B*128) | logpz (B) | logqz (B) ] fp32.
//
// CTA = 128 rows, 512 thr = 16 warps = 4 m-groups(32 rows) x 4 n-quarters(16).
// 1 CTA/SM (~202 KB smem) but same 16 warps/SM as the 379us champion.

#define ZZ 128
#define ZH 64
#define HS 50
#define NC 4
#define TPB 512
#define MR 128
#define PZ 68      // fp32 z pitch (floats)
#define KPI 36     // k-pair pitch (words)

// global packed-weight layout (per coupling), words
#define W0H 0                  // 56 n x 36 kp
#define W0L 2016
#define GW12 4032              // W1/W2 block starts here
#define W1Hr 0                 // offsets relative to W12 buffer
#define W1Lr 2304
#define W2Hr 4608
#define W2Lr 6912
#define WTOT 13248

// smem word offsets
#define OW0   0                // 4032 (single buffer)
#define OW12A 4032             // 9216
#define OW12B 13248            // 9216
#define OB    22464            // 2 x 192
#define OZ1   22848            // 128 x 68
#define OZ2   31552
#define OHH   40256            // 128 x 36
#define OHL   44864
#define OQ0   49472            // 128
#define OLD   49600            // 4 x 128
#define OSS   50112            // 4 x 128
#define SMEM_WORDS 50624
#define SMEM_BYTES (SMEM_WORDS * 4)    // 202496

__device__ __align__(16) unsigned gW[NC][WTOT];
__device__ __align__(16) float gBB[NC][192];

__device__ __forceinline__ float tanh_fast(float x) {
    float r;
    asm("tanh.approx.f32 %0, %1;" : "=f"(r) : "f"(x));
    return r;
}
__device__ __forceinline__ unsigned pack2(float hi_elem, float lo_elem) {
    unsigned r;
    asm("cvt.rn.bf16x2.f32 %0, %1, %2;" : "=r"(r) : "f"(hi_elem), "f"(lo_elem));
    return r;
}
// split (x = even-k, y = odd-k) into packed hi word + packed lo word
__device__ __forceinline__ void split2(float x, float y, unsigned& h, unsigned& l) {
    h = pack2(y, x);
    float hx = __uint_as_float(h << 16);
    float hy = __uint_as_float(h & 0xFFFF0000u);
    l = pack2(y - hy, x - hx);
}
__device__ __forceinline__ void mma16(float (&d)[4], const unsigned* a,
                                      unsigned b0, unsigned b1) {
    asm volatile(
        "mma.sync.aligned.m16n8k16.row.col.f32.bf16.bf16.f32 "
        "{%0,%1,%2,%3}, {%4,%5,%6,%7}, {%8,%9}, {%0,%1,%2,%3};"
        : "+f"(d[0]), "+f"(d[1]), "+f"(d[2]), "+f"(d[3])
        : "r"(a[0]), "r"(a[1]), "r"(a[2]), "r"(a[3]), "r"(b0), "r"(b1));
}
__device__ __forceinline__ void cp16(void* sdst, const void* gsrc) {
    unsigned s = (unsigned)__cvta_generic_to_shared(sdst);
    asm volatile("cp.async.cg.shared.global [%0], [%1], 16;" :: "r"(s), "l"(gsrc));
}
#define CP_COMMIT() asm volatile("cp.async.commit_group;" ::: "memory")
#define CP_WAIT0()  asm volatile("cp.async.wait_group 0;" ::: "memory")

// ---------------- pre-split kernel ----------------
__global__ void presplit_kernel(const float* __restrict__ W_in,  const float* __restrict__ b_in,
                                const float* __restrict__ W_mu,  const float* __restrict__ b_mu,
                                const float* __restrict__ W_sig, const float* __restrict__ b_sig)
{
    const int cc = blockIdx.x;
    const int tid = threadIdx.x;
    for (int idx = tid; idx < 56 * KPI; idx += blockDim.x) {
        int n = idx / KPI, kp = idx - n * KPI;
        int k0 = 2 * kp, k1 = k0 + 1;
        float v0 = (n < HS && k0 < ZH) ? W_in[cc * HS * ZH + n * ZH + k0] : 0.0f;
        float v1 = (n < HS && k1 < ZH) ? W_in[cc * HS * ZH + n * ZH + k1] : 0.0f;
        unsigned h, l;
        split2(v0, v1, h, l);
        gW[cc][W0H + idx] = h;
        gW[cc][W0L + idx] = l;
    }
    for (int idx = tid; idx < 64 * KPI; idx += blockDim.x) {
        int n = idx / KPI, kp = idx - n * KPI;
        int k0 = 2 * kp, k1 = k0 + 1;
        float m0 = (k0 < HS) ? W_mu [cc * ZH * HS + n * HS + k0] : 0.0f;
        float m1 = (k1 < HS) ? W_mu [cc * ZH * HS + n * HS + k1] : 0.0f;
        float s0 = (k0 < HS) ? W_sig[cc * ZH * HS + n * HS + k0] : 0.0f;
        float s1 = (k1 < HS) ? W_sig[cc * ZH * HS + n * HS + k1] : 0.0f;
        unsigned h, l;
        split2(m0, m1, h, l);
        gW[cc][GW12 + W1Hr + idx] = h;
        gW[cc][GW12 + W1Lr + idx] = l;
        split2(s0, s1, h, l);
        gW[cc][GW12 + W2Hr + idx] = h;
        gW[cc][GW12 + W2Lr + idx] = l;
    }
    if (tid < 64) {
        gBB[cc][tid]       = (tid < HS) ? b_in[cc * HS + tid] : 0.0f;
        gBB[cc][64 + tid]  = b_mu [cc * ZH + tid];
        gBB[cc][128 + tid] = b_sig[cc * ZH + tid];
    }
}

// ---------------- main kernel ----------------
__global__ void __launch_bounds__(TPB, 1)
flow_kernel(const float* __restrict__ mean,  const float* __restrict__ logvar,
            const float* __restrict__ eps,
            float* __restrict__ out, int Brows)
{
    extern __shared__ float sm[];
    unsigned* uW0 = (unsigned*)(sm + OW0);
    float*    sZ1 = sm + OZ1;
    float*    sZ2 = sm + OZ2;
    unsigned* uHH = (unsigned*)(sm + OHH);
    unsigned* uHL = (unsigned*)(sm + OHL);
    float*    sQ0 = sm + OQ0;
    float*    sLD = sm + OLD;
    float*    sSS = sm + OSS;

    const int tid  = threadIdx.x;
    const int lane = tid & 31;
    const int wid  = tid >> 5;
    const int wm   = wid & 3;          // m-group: rows 32*wm..+31
    const int wn   = wid >> 2;         // n-quarter (0..3)
    const int gid  = lane >> 2;
    const int tig  = lane & 3;
    const int rb   = 32 * wm;
    const int rowBase = blockIdx.x * MR;

    // ---- prefetch coupling 0: W0+biases (group), then W12 (group) ----
    {
        const float4* s0 = (const float4*)(&gW[0][0]);
        float4* d0 = (float4*)(sm + OW0);
        for (int i = tid; i < 4032 / 4; i += TPB) cp16(d0 + i, s0 + i);
        if (tid < 48) cp16((float4*)(sm + OB) + tid, (const float4*)(&gBB[0][0]) + tid);
        CP_COMMIT();
        const float4* s1 = (const float4*)(&gW[0][GW12]);
        float4* d1 = (float4*)(sm + OW12A);
        for (int i = tid; i < 9216 / 4; i += TPB) cp16(d1 + i, s1 + i);
        CP_COMMIT();
    }

    // ---- zero H k-pad (kp 28..31, all 128 rows) ----
    for (int i = tid; i < 512; i += TPB) {
        int r = i >> 2, kp = 28 + (i & 3);
        uHH[r * KPI + kp] = 0u;
        uHL[r * KPI + kp] = 0u;
    }

    // ================= reparam (4 threads/row) =================
    {
        const int rrow = tid >> 2, p = tid & 3;
        float part = 0.0f;
#pragma unroll
        for (int j = 0; j < 8; j++) {
            int q = p + 4 * j;
            size_t g = (size_t)(rowBase + rrow) * 32 + q;
            float4 mv = ((const float4*)mean  )[g];
            float4 lv = ((const float4*)logvar)[g];
            float4 ev = ((const float4*)eps   )[g];
            float4 z4;
            z4.x = fmaf(ev.x, __expf(0.5f * lv.x), mv.x);
            z4.y = fmaf(ev.y, __expf(0.5f * lv.y), mv.y);
            z4.z = fmaf(ev.z, __expf(0.5f * lv.z), mv.z);
            z4.w = fmaf(ev.w, __expf(0.5f * lv.w), mv.w);
            part += lv.x + lv.y + lv.z + lv.w;
            part = fmaf(ev.x, ev.x, part);
            part = fmaf(ev.y, ev.y, part);
            part = fmaf(ev.z, ev.z, part);
            part = fmaf(ev.w, ev.w, part);
            if (q < 16)
                *(float4*)&sZ1[rrow * PZ + 4 * q] = z4;
            else
                *(float4*)&sZ2[rrow * PZ + 4 * (q - 16)] = z4;
        }
        part += __shfl_xor_sync(0xffffffffu, part, 1);
        part += __shfl_xor_sync(0xffffffffu, part, 2);
        if (p == 0) sQ0[rrow] = -0.5f * part;
    }

    float ldp[4] = {0.f, 0.f, 0.f, 0.f};
    float ssp[4] = {0.f, 0.f, 0.f, 0.f};

    // ================= couplings =================
#pragma unroll 1
    for (int cc = 0; cc < NC; cc++) {
        CP_WAIT0();
        __syncthreads();               // W0(cc), b(cc), W12(cc), z, H-pad ready

        const unsigned* uW12 = (const unsigned*)(sm + ((cc & 1) ? OW12B : OW12A));
        const float* sB0 = sm + OB + 192 * (cc & 1);
        const float* sB1 = sB0 + 64;
        const float* sB2 = sB0 + 128;
        const float* sZa = (cc & 1) ? sZ2 : sZ1;
        float*       sZu = (cc & 1) ? sZ1 : sZ2;

        // ---- GEMM1: H = tanh(Za @ W0^T + b0); m32 x n16 (wn3: n8) ----
        {
            const int NT = (wn < 3) ? 2 : 1;   // 7 n-tiles over 4 quarters
            float acc[2][2][4] = {};
#pragma unroll
            for (int c = 0; c < 4; c++) {
                unsigned ah[2][4], al[2][4];
#pragma unroll
                for (int s2 = 0; s2 < 2; s2++) {
                    int ra0 = rb + 16 * s2 + gid, ra1 = ra0 + 8;
                    float2 v00 = ((const float2*)&sZa[ra0 * PZ])[tig +     8 * c];
                    float2 v10 = ((const float2*)&sZa[ra1 * PZ])[tig +     8 * c];
                    float2 v01 = ((const float2*)&sZa[ra0 * PZ])[tig + 4 + 8 * c];
                    float2 v11 = ((const float2*)&sZa[ra1 * PZ])[tig + 4 + 8 * c];
                    split2(v00.x, v00.y, ah[s2][0], al[s2][0]);
                    split2(v10.x, v10.y, ah[s2][1], al[s2][1]);
                    split2(v01.x, v01.y, ah[s2][2], al[s2][2]);
                    split2(v11.x, v11.y, ah[s2][3], al[s2][3]);
                }
#pragma unroll
                for (int nn = 0; nn < 2; nn++) {
                    if (nn >= NT) break;
                    int nrow = 8 * (2 * wn + nn) + gid;
                    unsigned bh0 = uW0[W0H + nrow * KPI + tig +     8 * c];
                    unsigned bh1 = uW0[W0H + nrow * KPI + tig + 4 + 8 * c];
                    unsigned bl0 = uW0[W0L + nrow * KPI + tig +     8 * c];
                    unsigned bl1 = uW0[W0L + nrow * KPI + tig + 4 + 8 * c];
#pragma unroll
                    for (int s2 = 0; s2 < 2; s2++) {
                        mma16(acc[s2][nn], ah[s2], bh0, bh1);
                        mma16(acc[s2][nn], ah[s2], bl0, bl1);
                        mma16(acc[s2][nn], al[s2], bh0, bh1);
                    }
                }
            }
            // epilogue: bias + tanh, write H pre-split/packed
#pragma unroll
            for (int nn = 0; nn < 2; nn++) {
                if (nn >= NT) break;
                int nt  = 2 * wn + nn;
                int col = 8 * nt + 2 * tig;
                int kp  = 4 * nt + tig;
                float bb0 = sB0[col], bb1 = sB0[col + 1];
#pragma unroll
                for (int s2 = 0; s2 < 2; s2++) {
                    int ra0 = rb + 16 * s2 + gid, ra1 = ra0 + 8;
                    float t00 = tanh_fast(acc[s2][nn][0] + bb0);
                    float t01 = tanh_fast(acc[s2][nn][1] + bb1);
                    float t10 = tanh_fast(acc[s2][nn][2] + bb0);
                    float t11 = tanh_fast(acc[s2][nn][3] + bb1);
                    unsigned h, l;
                    split2(t00, t01, h, l);
                    uHH[ra0 * KPI + kp] = h;
                    uHL[ra0 * KPI + kp] = l;
                    split2(t10, t11, h, l);
                    uHH[ra1 * KPI + kp] = h;
                    uHL[ra1 * KPI + kp] = l;
                }
            }
        }
        __syncthreads();               // H complete; W0(cc) reads done

        // ---- prefetch next coupling (overlaps GEMM2) ----
        if (cc < 3) {
            int nb = (cc + 1) & 1;
            const float4* s0 = (const float4*)(&gW[cc + 1][0]);
            float4* d0 = (float4*)(sm + OW0);
            for (int i = tid; i < 4032 / 4; i += TPB) cp16(d0 + i, s0 + i);
            if (tid < 48)
                cp16((float4*)(sm + OB + 192 * nb) + tid,
                     (const float4*)(&gBB[cc + 1][0]) + tid);
            const float4* s1 = (const float4*)(&gW[cc + 1][GW12]);
            float4* d1 = (float4*)(sm + (nb ? OW12B : OW12A));
            for (int i = tid; i < 9216 / 4; i += TPB) cp16(d1 + i, s1 + i);
            CP_COMMIT();
        }

        // ---- GEMM2: mu/sig heads; m32 x n16 (2 tiles), K=64 ----
        {
            float am [2][2][4] = {};
            float as2[2][2][4] = {};
#pragma unroll
            for (int c = 0; c < 4; c++) {
                unsigned ah[2][4], al[2][4];
#pragma unroll
                for (int s2 = 0; s2 < 2; s2++) {
                    int ra0 = rb + 16 * s2 + gid, ra1 = ra0 + 8;
                    ah[s2][0] = uHH[ra0 * KPI + tig +     8 * c];
                    ah[s2][1] = uHH[ra1 * KPI + tig +     8 * c];
                    ah[s2][2] = uHH[ra0 * KPI + tig + 4 + 8 * c];
                    ah[s2][3] = uHH[ra1 * KPI + tig + 4 + 8 * c];
                    al[s2][0] = uHL[ra0 * KPI + tig +     8 * c];
                    al[s2][1] = uHL[ra1 * KPI + tig +     8 * c];
                    al[s2][2] = uHL[ra0 * KPI + tig + 4 + 8 * c];
                    al[s2][3] = uHL[ra1 * KPI + tig + 4 + 8 * c];
                }
#pragma unroll
                for (int nn = 0; nn < 2; nn++) {
                    int nrow = 8 * (2 * wn + nn) + gid;
                    unsigned bh0 = uW12[W1Hr + nrow * KPI + tig +     8 * c];
                    unsigned bh1 = uW12[W1Hr + nrow * KPI + tig + 4 + 8 * c];
                    unsigned bl0 = uW12[W1Lr + nrow * KPI + tig +     8 * c];
                    unsigned bl1 = uW12[W1Lr + nrow * KPI + tig + 4 + 8 * c];
#pragma unroll
                    for (int s2 = 0; s2 < 2; s2++) {
                        mma16(am[s2][nn], ah[s2], bh0, bh1);
                        mma16(am[s2][nn], ah[s2], bl0, bl1);
                        mma16(am[s2][nn], al[s2], bh0, bh1);
                    }
                    bh0 = uW12[W2Hr + nrow * KPI + tig +     8 * c];
                    bh1 = uW12[W2Hr + nrow * KPI + tig + 4 + 8 * c];
                    bl0 = uW12[W2Lr + nrow * KPI + tig +     8 * c];
                    bl1 = uW12[W2Lr + nrow * KPI + tig + 4 + 8 * c];
#pragma unroll
                    for (int s2 = 0; s2 < 2; s2++) {
                        mma16(as2[s2][nn], ah[s2], bh0, bh1);
                        mma16(as2[s2][nn], ah[s2], bl0, bl1);
                        mma16(as2[s2][nn], al[s2], bh0, bh1);
                    }
                }
            }
            // ---- epilogue: sig, z update, logdet ----
            const bool fin = (cc >= 2);
#pragma unroll
            for (int s2 = 0; s2 < 2; s2++) {
                int ra0 = rb + 16 * s2 + gid, ra1 = ra0 + 8;
#pragma unroll
                for (int nn = 0; nn < 2; nn++) {
                    int col = 8 * (2 * wn + nn) + 2 * tig;
#pragma unroll
                    for (int d = 0; d < 2; d++) {
                        float bm = sB1[col + d];
                        float bs = sB2[col + d];
                        {
                            float mu = am[s2][nn][d] + bm;
                            float x  = as2[s2][nn][d] + bs;
                            float sg = fmaf(tanh_fast(0.5f * x), 0.5f, 0.5f);
                            ldp[2 * s2] += __logf(sg);
                            float zn = fmaf(sZu[ra0 * PZ + col + d], sg, mu);
                            sZu[ra0 * PZ + col + d] = zn;
                            if (fin) ssp[2 * s2] = fmaf(zn, zn, ssp[2 * s2]);
                        }
                        {
                            float mu = am[s2][nn][d + 2] + bm;
                            float x  = as2[s2][nn][d + 2] + bs;
                            float sg = fmaf(tanh_fast(0.5f * x), 0.5f, 0.5f);
                            ldp[2 * s2 + 1] += __logf(sg);
                            float zn = fmaf(sZu[ra1 * PZ + col + d], sg, mu);
                            sZu[ra1 * PZ + col + d] = zn;
                            if (fin) ssp[2 * s2 + 1] = fmaf(zn, zn, ssp[2 * s2 + 1]);
                        }
                    }
                }
            }
        }
        __syncthreads();               // z updated before next GEMM1 / final write
    }

    // ================= write z (coalesced float4) =================
#pragma unroll
    for (int i = 0; i < 8; i++) {
        int idx = tid + TPB * i;            // 0..4095
        int row = idx >> 5, q = idx & 31;
        float4 v = (q < 16)
            ? *(const float4*)&sZ1[row * PZ + 4 * q]
            : *(const float4*)&sZ2[row * PZ + 4 * (q - 16)];
        ((float4*)out)[(size_t)(rowBase + row) * 32 + q] = v;
    }

    // ================= densities =================
#pragma unroll
    for (int s = 0; s < 4; s++) {
        float l = ldp[s], v = ssp[s];
        l += __shfl_xor_sync(0xffffffffu, l, 1);
        l += __shfl_xor_sync(0xffffffffu, l, 2);
        v += __shfl_xor_sync(0xffffffffu, v, 1);
        v += __shfl_xor_sync(0xffffffffu, v, 2);
        if (tig == 0) {
            int row = rb + 16 * (s >> 1) + 8 * (s & 1) + gid;
            sLD[wn * 128 + row] = l;
            sSS[wn * 128 + row] = v;
        }
    }
    __syncthreads();
    if (tid < 128) {
        float l = sLD[tid] + sLD[128 + tid] + sLD[256 + tid] + sLD[384 + tid];
        float s = sSS[tid] + sSS[128 + tid] + sSS[256 + tid] + sSS[384 + tid];
        size_t base = (size_t)Brows * ZZ;
        out[base + rowBase + tid]         = -0.5f * s;
        out[base + Brows + rowBase + tid] = sQ0[tid] - l;
    }
}

extern "C" void kernel_launch(void* const* d_in, const int* in_sizes, int n_in,
                              void* d_out, int out_size)
{
    const float* mean   = (const float*)d_in[0];
    const float* logvar = (const float*)d_in[1];
    const float* eps    = (const float*)d_in[2];
    const float* W_in   = (const float*)d_in[3];
    const float* b_in   = (const float*)d_in[4];
    const float* W_mu   = (const float*)d_in[5];
    const float* b_mu   = (const float*)d_in[6];
    const float* W_sig  = (const float*)d_in[7];
    const float* b_sig  = (const float*)d_in[8];
    float* out = (float*)d_out;

    int Brows = in_sizes[0] / ZZ;

    cudaFuncSetAttribute(flow_kernel, cudaFuncAttributeMaxDynamicSharedMemorySize, SMEM_BYTES);

    presplit_kernel<<<NC, 256>>>(W_in, b_in, W_mu, b_mu, W_sig, b_sig);
    flow_kernel<<<Brows / MR, TPB, SMEM_BYTES>>>(mean, logvar, eps, out, Brows);
}

// round 12
// speedup vs baseline: 1.1949x; 1.1326x over previous
#include <cuda_runtime.h>
#include <cstdint>

// Flow1 via mma.sync m16n8k16 bf16 (3-product compensation), packed pre-split
// weights, m32 x n16 warp tiles at 2 CTAs/SM, group-counted cp.async staging.
// B=262144 rows, Z=128, ZH=64, HS=50 (padded 56), 4 couplings.
// Out: [ z (B*128) | logpz (B) | logqz (B) ] fp32.
//
// CTA = 64 rows, 256 thr = 8 warps = 2 m-groups(32 rows) x 4 n-quarters(16).
// Single weight buffer (110 KB total smem -> 2 CTAs/SM = 16 warps/SM);
// cp.async groups: {W0,b} waited at GEMM1, {W12} waited only at GEMM2.

#define ZZ 128
#define ZH 64
#define HS 50
#define NC 4
#define TPB 256
#define MR 64
#define PZ 68      // fp32 z pitch (floats)
#define KPI 36     // k-pair pitch (words)

// global packed-weight layout (per coupling), words
#define W0H 0                  // 56 n x 36 kp
#define W0L 2016
#define GW12 4032              // W1/W2 block
#define W1Hr 0
#define W1Lr 2304
#define W2Hr 4608
#define W2Lr 6912
#define WTOT 13248

// smem word offsets
#define OW0   0                // 4032
#define OW12  4032             // 9216
#define OB    13248            // 2 x 192 (bias double buffer)
#define OZ1   13632            // 64 x 68
#define OZ2   17984
#define OHH   22336            // 64 x 36
#define OHL   24640
#define OQ0   26944            // 64
#define OLD   27008            // 4 x 64
#define OSS   27264            // 4 x 64
#define SMEM_WORDS 27520
#define SMEM_BYTES (SMEM_WORDS * 4)    // 110080 -> 2 CTAs/SM

__device__ __align__(16) unsigned gW[NC][WTOT];
__device__ __align__(16) float gBB[NC][192];

__device__ __forceinline__ float tanh_fast(float x) {
    float r;
    asm("tanh.approx.f32 %0, %1;" : "=f"(r) : "f"(x));
    return r;
}
__device__ __forceinline__ unsigned pack2(float hi_elem, float lo_elem) {
    unsigned r;
    asm("cvt.rn.bf16x2.f32 %0, %1, %2;" : "=r"(r) : "f"(hi_elem), "f"(lo_elem));
    return r;
}
// split (x = even-k, y = odd-k) into packed hi word + packed lo word
__device__ __forceinline__ void split2(float x, float y, unsigned& h, unsigned& l) {
    h = pack2(y, x);
    float hx = __uint_as_float(h << 16);
    float hy = __uint_as_float(h & 0xFFFF0000u);
    l = pack2(y - hy, x - hx);
}
__device__ __forceinline__ void mma16(float (&d)[4], const unsigned* a,
                                      unsigned b0, unsigned b1) {
    asm volatile(
        "mma.sync.aligned.m16n8k16.row.col.f32.bf16.bf16.f32 "
        "{%0,%1,%2,%3}, {%4,%5,%6,%7}, {%8,%9}, {%0,%1,%2,%3};"
        : "+f"(d[0]), "+f"(d[1]), "+f"(d[2]), "+f"(d[3])
        : "r"(a[0]), "r"(a[1]), "r"(a[2]), "r"(a[3]), "r"(b0), "r"(b1));
}
__device__ __forceinline__ void cp16(void* sdst, const void* gsrc) {
    unsigned s = (unsigned)__cvta_generic_to_shared(sdst);
    asm volatile("cp.async.cg.shared.global [%0], [%1], 16;" :: "r"(s), "l"(gsrc));
}
#define CP_COMMIT() asm volatile("cp.async.commit_group;" ::: "memory")
#define CP_WAIT0()  asm volatile("cp.async.wait_group 0;" ::: "memory")
#define CP_WAIT1()  asm volatile("cp.async.wait_group 1;" ::: "memory")

// ---------------- pre-split kernel ----------------
__global__ void presplit_kernel(const float* __restrict__ W_in,  const float* __restrict__ b_in,
                                const float* __restrict__ W_mu,  const float* __restrict__ b_mu,
                                const float* __restrict__ W_sig, const float* __restrict__ b_sig)
{
    const int cc = blockIdx.x;
    const int tid = threadIdx.x;
    for (int idx = tid; idx < 56 * KPI; idx += blockDim.x) {
        int n = idx / KPI, kp = idx - n * KPI;
        int k0 = 2 * kp, k1 = k0 + 1;
        float v0 = (n < HS && k0 < ZH) ? W_in[cc * HS * ZH + n * ZH + k0] : 0.0f;
        float v1 = (n < HS && k1 < ZH) ? W_in[cc * HS * ZH + n * ZH + k1] : 0.0f;
        unsigned h, l;
        split2(v0, v1, h, l);
        gW[cc][W0H + idx] = h;
        gW[cc][W0L + idx] = l;
    }
    for (int idx = tid; idx < 64 * KPI; idx += blockDim.x) {
        int n = idx / KPI, kp = idx - n * KPI;
        int k0 = 2 * kp, k1 = k0 + 1;
        float m0 = (k0 < HS) ? W_mu [cc * ZH * HS + n * HS + k0] : 0.0f;
        float m1 = (k1 < HS) ? W_mu [cc * ZH * HS + n * HS + k1] : 0.0f;
        float s0 = (k0 < HS) ? W_sig[cc * ZH * HS + n * HS + k0] : 0.0f;
        float s1 = (k1 < HS) ? W_sig[cc * ZH * HS + n * HS + k1] : 0.0f;
        unsigned h, l;
        split2(m0, m1, h, l);
        gW[cc][GW12 + W1Hr + idx] = h;
        gW[cc][GW12 + W1Lr + idx] = l;
        split2(s0, s1, h, l);
        gW[cc][GW12 + W2Hr + idx] = h;
        gW[cc][GW12 + W2Lr + idx] = l;
    }
    if (tid < 64) {
        gBB[cc][tid]       = (tid < HS) ? b_in[cc * HS + tid] : 0.0f;
        gBB[cc][64 + tid]  = b_mu [cc * ZH + tid];
        gBB[cc][128 + tid] = b_sig[cc * ZH + tid];
    }
}

// ---------------- main kernel ----------------
__global__ void __launch_bounds__(TPB, 2)
flow_kernel(const float* __restrict__ mean,  const float* __restrict__ logvar,
            const float* __restrict__ eps,
            float* __restrict__ out, int Brows)
{
    extern __shared__ float sm[];
    unsigned* uW0  = (unsigned*)(sm + OW0);
    unsigned* uW12 = (unsigned*)(sm + OW12);
    float*    sZ1  = sm + OZ1;
    float*    sZ2  = sm + OZ2;
    unsigned* uHH  = (unsigned*)(sm + OHH);
    unsigned* uHL  = (unsigned*)(sm + OHL);
    float*    sQ0  = sm + OQ0;
    float*    sLD  = sm + OLD;
    float*    sSS  = sm + OSS;

    const int tid  = threadIdx.x;
    const int lane = tid & 31;
    const int wid  = tid >> 5;
    const int wm   = wid & 1;          // m-group: rows 32*wm..+31
    const int wn   = wid >> 1;         // n-quarter (0..3)
    const int gid  = lane >> 2;
    const int tig  = lane & 3;
    const int rb   = 32 * wm;
    const int rowBase = blockIdx.x * MR;

    // ---- prefetch coupling 0: group A = {W0,b}, group B = {W12} ----
    {
        const float4* s0 = (const float4*)(&gW[0][0]);
        float4* d0 = (float4*)(sm + OW0);
        for (int i = tid; i < 4032 / 4; i += TPB) cp16(d0 + i, s0 + i);
        if (tid < 48) cp16((float4*)(sm + OB) + tid, (const float4*)(&gBB[0][0]) + tid);
        CP_COMMIT();
        const float4* s1 = (const float4*)(&gW[0][GW12]);
        float4* d1 = (float4*)(sm + OW12);
        for (int i = tid; i < 9216 / 4; i += TPB) cp16(d1 + i, s1 + i);
        CP_COMMIT();
    }

    // ---- zero H k-pad (kp 28..31, 64 rows) ----
    if (tid < 256) {
        int r = tid >> 2, kp = 28 + (tid & 3);
        uHH[r * KPI + kp] = 0u;
        uHL[r * KPI + kp] = 0u;
    }

    // ================= reparam (4 threads/row) =================
    {
        const int rrow = tid >> 2, p = tid & 3;
        float part = 0.0f;
#pragma unroll
        for (int j = 0; j < 8; j++) {
            int q = p + 4 * j;
            size_t g = (size_t)(rowBase + rrow) * 32 + q;
            float4 mv = ((const float4*)mean  )[g];
            float4 lv = ((const float4*)logvar)[g];
            float4 ev = ((const float4*)eps   )[g];
            float4 z4;
            z4.x = fmaf(ev.x, __expf(0.5f * lv.x), mv.x);
            z4.y = fmaf(ev.y, __expf(0.5f * lv.y), mv.y);
            z4.z = fmaf(ev.z, __expf(0.5f * lv.z), mv.z);
            z4.w = fmaf(ev.w, __expf(0.5f * lv.w), mv.w);
            part += lv.x + lv.y + lv.z + lv.w;
            part = fmaf(ev.x, ev.x, part);
            part = fmaf(ev.y, ev.y, part);
            part = fmaf(ev.z, ev.z, part);
            part = fmaf(ev.w, ev.w, part);
            if (q < 16)
                *(float4*)&sZ1[rrow * PZ + 4 * q] = z4;
            else
                *(float4*)&sZ2[rrow * PZ + 4 * (q - 16)] = z4;
        }
        part += __shfl_xor_sync(0xffffffffu, part, 1);
        part += __shfl_xor_sync(0xffffffffu, part, 2);
        if (p == 0) sQ0[rrow] = -0.5f * part;
    }

    float ldp[4] = {0.f, 0.f, 0.f, 0.f};
    float ssp[4] = {0.f, 0.f, 0.f, 0.f};

    // ================= couplings =================
#pragma unroll 1
    for (int cc = 0; cc < NC; cc++) {
        // wait group A of cc ({W0,b}); group B ({W12}) may still stream
        CP_WAIT1();
        __syncthreads();

        const float* sB0 = sm + OB + 192 * (cc & 1);
        const float* sB1 = sB0 + 64;
        const float* sB2 = sB0 + 128;
        const float* sZa = (cc & 1) ? sZ2 : sZ1;
        float*       sZu = (cc & 1) ? sZ1 : sZ2;

        // ---- GEMM1: H = tanh(Za @ W0^T + b0); m32 x n16 (wn3: n8) ----
        {
            const int NT = (wn < 3) ? 2 : 1;   // 7 n-tiles over 4 quarters
            float acc[2][2][4] = {};
#pragma unroll
            for (int c = 0; c < 4; c++) {
                unsigned ah[2][4], al[2][4];
#pragma unroll
                for (int s2 = 0; s2 < 2; s2++) {
                    int ra0 = rb + 16 * s2 + gid, ra1 = ra0 + 8;
                    float2 v00 = ((const float2*)&sZa[ra0 * PZ])[tig +     8 * c];
                    float2 v10 = ((const float2*)&sZa[ra1 * PZ])[tig +     8 * c];
                    float2 v01 = ((const float2*)&sZa[ra0 * PZ])[tig + 4 + 8 * c];
                    float2 v11 = ((const float2*)&sZa[ra1 * PZ])[tig + 4 + 8 * c];
                    split2(v00.x, v00.y, ah[s2][0], al[s2][0]);
                    split2(v10.x, v10.y, ah[s2][1], al[s2][1]);
                    split2(v01.x, v01.y, ah[s2][2], al[s2][2]);
                    split2(v11.x, v11.y, ah[s2][3], al[s2][3]);
                }
#pragma unroll
                for (int nn = 0; nn < 2; nn++) {
                    if (nn >= NT) break;
                    int nrow = 8 * (2 * wn + nn) + gid;
                    unsigned bh0 = uW0[W0H + nrow * KPI + tig +     8 * c];
                    unsigned bh1 = uW0[W0H + nrow * KPI + tig + 4 + 8 * c];
                    unsigned bl0 = uW0[W0L + nrow * KPI + tig +     8 * c];
                    unsigned bl1 = uW0[W0L + nrow * KPI + tig + 4 + 8 * c];
#pragma unroll
                    for (int s2 = 0; s2 < 2; s2++) {
                        mma16(acc[s2][nn], ah[s2], bh0, bh1);
                        mma16(acc[s2][nn], ah[s2], bl0, bl1);
                        mma16(acc[s2][nn], al[s2], bh0, bh1);
                    }
                }
            }
            // epilogue: bias + tanh, write H pre-split/packed
#pragma unroll
            for (int nn = 0; nn < 2; nn++) {
                if (nn >= NT) break;
                int nt  = 2 * wn + nn;
                int col = 8 * nt + 2 * tig;
                int kp  = 4 * nt + tig;
                float bb0 = sB0[col], bb1 = sB0[col + 1];
#pragma unroll
                for (int s2 = 0; s2 < 2; s2++) {
                    int ra0 = rb + 16 * s2 + gid, ra1 = ra0 + 8;
                    float t00 = tanh_fast(acc[s2][nn][0] + bb0);
                    float t01 = tanh_fast(acc[s2][nn][1] + bb1);
                    float t10 = tanh_fast(acc[s2][nn][2] + bb0);
                    float t11 = tanh_fast(acc[s2][nn][3] + bb1);
                    unsigned h, l;
                    split2(t00, t01, h, l);
                    uHH[ra0 * KPI + kp] = h;
                    uHL[ra0 * KPI + kp] = l;
                    split2(t10, t11, h, l);
                    uHH[ra1 * KPI + kp] = h;
                    uHL[ra1 * KPI + kp] = l;
                }
            }
        }
        CP_WAIT0();                    // W12(cc) landed
        __syncthreads();               // H visible; W0(cc) reads done

        // ---- prefetch {W0,b}(cc+1) (overlaps GEMM2; W0 buffer now free) ----
        if (cc < 3) {
            const float4* s0 = (const float4*)(&gW[cc + 1][0]);
            float4* d0 = (float4*)(sm + OW0);
            for (int i = tid; i < 4032 / 4; i += TPB) cp16(d0 + i, s0 + i);
            if (tid < 48)
                cp16((float4*)(sm + OB + 192 * ((cc + 1) & 1)) + tid,
                     (const float4*)(&gBB[cc + 1][0]) + tid);
            CP_COMMIT();
        }

        // ---- GEMM2: mu/sig heads; m32 x n16 (2 tiles), K=64 ----
        {
            float am [2][2][4] = {};
            float as2[2][2][4] = {};
#pragma unroll
            for (int c = 0; c < 4; c++) {
                unsigned ah[2][4], al[2][4];
#pragma unroll
                for (int s2 = 0; s2 < 2; s2++) {
                    int ra0 = rb + 16 * s2 + gid, ra1 = ra0 + 8;
                    ah[s2][0] = uHH[ra0 * KPI + tig +     8 * c];
                    ah[s2][1] = uHH[ra1 * KPI + tig +     8 * c];
                    ah[s2][2] = uHH[ra0 * KPI + tig + 4 + 8 * c];
                    ah[s2][3] = uHH[ra1 * KPI + tig + 4 + 8 * c];
                    al[s2][0] = uHL[ra0 * KPI + tig +     8 * c];
                    al[s2][1] = uHL[ra1 * KPI + tig +     8 * c];
                    al[s2][2] = uHL[ra0 * KPI + tig + 4 + 8 * c];
                    al[s2][3] = uHL[ra1 * KPI + tig + 4 + 8 * c];
                }
#pragma unroll
                for (int nn = 0; nn < 2; nn++) {
                    int nrow = 8 * (2 * wn + nn) + gid;
                    unsigned bh0 = uW12[W1Hr + nrow * KPI + tig +     8 * c];
                    unsigned bh1 = uW12[W1Hr + nrow * KPI + tig + 4 + 8 * c];
                    unsigned bl0 = uW12[W1Lr + nrow * KPI + tig +     8 * c];
                    unsigned bl1 = uW12[W1Lr + nrow * KPI + tig + 4 + 8 * c];
#pragma unroll
                    for (int s2 = 0; s2 < 2; s2++) {
                        mma16(am[s2][nn], ah[s2], bh0, bh1);
                        mma16(am[s2][nn], ah[s2], bl0, bl1);
                        mma16(am[s2][nn], al[s2], bh0, bh1);
                    }
                    bh0 = uW12[W2Hr + nrow * KPI + tig +     8 * c];
                    bh1 = uW12[W2Hr + nrow * KPI + tig + 4 + 8 * c];
                    bl0 = uW12[W2Lr + nrow * KPI + tig +     8 * c];
                    bl1 = uW12[W2Lr + nrow * KPI + tig + 4 + 8 * c];
#pragma unroll
                    for (int s2 = 0; s2 < 2; s2++) {
                        mma16(as2[s2][nn], ah[s2], bh0, bh1);
                        mma16(as2[s2][nn], ah[s2], bl0, bl1);
                        mma16(as2[s2][nn], al[s2], bh0, bh1);
                    }
                }
            }
            // ---- epilogue: sig, z update, logdet ----
            const bool fin = (cc >= 2);
#pragma unroll
            for (int s2 = 0; s2 < 2; s2++) {
                int ra0 = rb + 16 * s2 + gid, ra1 = ra0 + 8;
#pragma unroll
                for (int nn = 0; nn < 2; nn++) {
                    int col = 8 * (2 * wn + nn) + 2 * tig;
#pragma unroll
                    for (int d = 0; d < 2; d++) {
                        float bm = sB1[col + d];
                        float bs = sB2[col + d];
                        {
                            float mu = am[s2][nn][d] + bm;
                            float x  = as2[s2][nn][d] + bs;
                            float sg = fmaf(tanh_fast(0.5f * x), 0.5f, 0.5f);
                            ldp[2 * s2] += __logf(sg);
                            float zn = fmaf(sZu[ra0 * PZ + col + d], sg, mu);
                            sZu[ra0 * PZ + col + d] = zn;
                            if (fin) ssp[2 * s2] = fmaf(zn, zn, ssp[2 * s2]);
                        }
                        {
                            float mu = am[s2][nn][d + 2] + bm;
                            float x  = as2[s2][nn][d + 2] + bs;
                            float sg = fmaf(tanh_fast(0.5f * x), 0.5f, 0.5f);
                            ldp[2 * s2 + 1] += __logf(sg);
                            float zn = fmaf(sZu[ra1 * PZ + col + d], sg, mu);
                            sZu[ra1 * PZ + col + d] = zn;
                            if (fin) ssp[2 * s2 + 1] = fmaf(zn, zn, ssp[2 * s2 + 1]);
                        }
                    }
                }
            }
        }
        __syncthreads();               // z updated; W12(cc) reads done

        // ---- prefetch {W12}(cc+1) (overlaps next GEMM1) ----
        if (cc < 3) {
            const float4* s1 = (const float4*)(&gW[cc + 1][GW12]);
            float4* d1 = (float4*)(sm + OW12);
            for (int i = tid; i < 9216 / 4; i += TPB) cp16(d1 + i, s1 + i);
            CP_COMMIT();
        }
    }

    // ================= write z (coalesced float4) =================
#pragma unroll
    for (int i = 0; i < 8; i++) {
        int idx = tid + TPB * i;            // 0..2047
        int row = idx >> 5, q = idx & 31;
        float4 v = (q < 16)
            ? *(const float4*)&sZ1[row * PZ + 4 * q]
            : *(const float4*)&sZ2[row * PZ + 4 * (q - 16)];
        ((float4*)out)[(size_t)(rowBase + row) * 32 + q] = v;
    }

    // ================= densities =================
#pragma unroll
    for (int s = 0; s < 4; s++) {
        float l = ldp[s], v = ssp[s];
        l += __shfl_xor_sync(0xffffffffu, l, 1);
        l += __shfl_xor_sync(0xffffffffu, l, 2);
        v += __shfl_xor_sync(0xffffffffu, v, 1);
        v += __shfl_xor_sync(0xffffffffu, v, 2);
        if (tig == 0) {
            int row = rb + 16 * (s >> 1) + 8 * (s & 1) + gid;
            sLD[wn * 64 + row] = l;
            sSS[wn * 64 + row] = v;
        }
    }
    __syncthreads();
    if (tid < 64) {
        float l = sLD[tid] + sLD[64 + tid] + sLD[128 + tid] + sLD[192 + tid];
        float s = sSS[tid] + sSS[64 + tid] + sSS[128 + tid] + sSS[192 + tid];
        size_t base = (size_t)Brows * ZZ;
        out[base + rowBase + tid]         = -0.5f * s;
        out[base + Brows + rowBase + tid] = sQ0[tid] - l;
    }
}

extern "C" void kernel_launch(void* const* d_in, const int* in_sizes, int n_in,
                              void* d_out, int out_size)
{
    const float* mean   = (const float*)d_in[0];
    const float* logvar = (const float*)d_in[1];
    const float* eps    = (const float*)d_in[2];
    const float* W_in   = (const float*)d_in[3];
    const float* b_in   = (const float*)d_in[4];
    const float* W_mu   = (const float*)d_in[5];
    const float* b_mu   = (const float*)d_in[6];
    const float* W_sig  = (const float*)d_in[7];
    const float* b_sig  = (const float*)d_in[8];
    float* out = (float*)d_out;

    int Brows = in_sizes[0] / ZZ;

    cudaFuncSetAttribute(flow_kernel, cudaFuncAttributeMaxDynamicSharedMemorySize, SMEM_BYTES);

    presplit_kernel<<<NC, 256>>>(W_in, b_in, W_mu, b_mu, W_sig, b_sig);
    flow_kernel<<<Brows / MR, TPB, SMEM_BYTES>>>(mean, logvar, eps, out, Brows);
}

// round 13
// speedup vs baseline: 1.2423x; 1.0397x over previous
#include <cuda_runtime.h>
#include <cstdint>

// Flow1 via mma.sync m16n8k16 bf16 (3-product compensation), packed pre-split
// weights, m32 x n16 warp tiles at 2 CTAs/SM, group-counted cp.async staging.
// R13: z pitch 68 -> 72 so LDS.64 A-loads and epilogue z accesses are
// bank-conflict-free (68 gave 2-way conflicts on all 64-bit accesses).
// B=262144 rows, Z=128, ZH=64, HS=50 (padded 56), 4 couplings.
// Out: [ z (B*128) | logpz (B) | logqz (B) ] fp32.

#define ZZ 128
#define ZH 64
#define HS 50
#define NC 4
#define TPB 256
#define MR 64
#define PZ 72      // fp32 z pitch (floats); 72 % 32 = 8 -> conflict-free LDS.64
#define KPI 36     // k-pair pitch (words)

// global packed-weight layout (per coupling), words
#define W0H 0                  // 56 n x 36 kp
#define W0L 2016
#define GW12 4032              // W1/W2 block
#define W1Hr 0
#define W1Lr 2304
#define W2Hr 4608
#define W2Lr 6912
#define WTOT 13248

// smem word offsets
#define OW0   0                // 4032
#define OW12  4032             // 9216
#define OB    13248            // 2 x 192 (bias double buffer)
#define OZ1   13632            // 64 x 72
#define OZ2   18240
#define OHH   22848            // 64 x 36
#define OHL   25152
#define OQ0   27456            // 64
#define OLD   27520            // 4 x 64
#define OSS   27776            // 4 x 64
#define SMEM_WORDS 28032
#define SMEM_BYTES (SMEM_WORDS * 4)    // 112128 -> 2 CTAs/SM (224.3 KB < 228 KB)

__device__ __align__(16) unsigned gW[NC][WTOT];
__device__ __align__(16) float gBB[NC][192];

__device__ __forceinline__ float tanh_fast(float x) {
    float r;
    asm("tanh.approx.f32 %0, %1;" : "=f"(r) : "f"(x));
    return r;
}
__device__ __forceinline__ unsigned pack2(float hi_elem, float lo_elem) {
    unsigned r;
    asm("cvt.rn.bf16x2.f32 %0, %1, %2;" : "=r"(r) : "f"(hi_elem), "f"(lo_elem));
    return r;
}
// split (x = even-k, y = odd-k) into packed hi word + packed lo word
__device__ __forceinline__ void split2(float x, float y, unsigned& h, unsigned& l) {
    h = pack2(y, x);
    float hx = __uint_as_float(h << 16);
    float hy = __uint_as_float(h & 0xFFFF0000u);
    l = pack2(y - hy, x - hx);
}
__device__ __forceinline__ void mma16(float (&d)[4], const unsigned* a,
                                      unsigned b0, unsigned b1) {
    asm volatile(
        "mma.sync.aligned.m16n8k16.row.col.f32.bf16.bf16.f32 "
        "{%0,%1,%2,%3}, {%4,%5,%6,%7}, {%8,%9}, {%0,%1,%2,%3};"
        : "+f"(d[0]), "+f"(d[1]), "+f"(d[2]), "+f"(d[3])
        : "r"(a[0]), "r"(a[1]), "r"(a[2]), "r"(a[3]), "r"(b0), "r"(b1));
}
__device__ __forceinline__ void cp16(void* sdst, const void* gsrc) {
    unsigned s = (unsigned)__cvta_generic_to_shared(sdst);
    asm volatile("cp.async.cg.shared.global [%0], [%1], 16;" :: "r"(s), "l"(gsrc));
}
#define CP_COMMIT() asm volatile("cp.async.commit_group;" ::: "memory")
#define CP_WAIT0()  asm volatile("cp.async.wait_group 0;" ::: "memory")
#define CP_WAIT1()  asm volatile("cp.async.wait_group 1;" ::: "memory")

// ---------------- pre-split kernel ----------------
__global__ void presplit_kernel(const float* __restrict__ W_in,  const float* __restrict__ b_in,
                                const float* __restrict__ W_mu,  const float* __restrict__ b_mu,
                                const float* __restrict__ W_sig, const float* __restrict__ b_sig)
{
    const int cc = blockIdx.x;
    const int tid = threadIdx.x;
    for (int idx = tid; idx < 56 * KPI; idx += blockDim.x) {
        int n = idx / KPI, kp = idx - n * KPI;
        int k0 = 2 * kp, k1 = k0 + 1;
        float v0 = (n < HS && k0 < ZH) ? W_in[cc * HS * ZH + n * ZH + k0] : 0.0f;
        float v1 = (n < HS && k1 < ZH) ? W_in[cc * HS * ZH + n * ZH + k1] : 0.0f;
        unsigned h, l;
        split2(v0, v1, h, l);
        gW[cc][W0H + idx] = h;
        gW[cc][W0L + idx] = l;
    }
    for (int idx = tid; idx < 64 * KPI; idx += blockDim.x) {
        int n = idx / KPI, kp = idx - n * KPI;
        int k0 = 2 * kp, k1 = k0 + 1;
        float m0 = (k0 < HS) ? W_mu [cc * ZH * HS + n * HS + k0] : 0.0f;
        float m1 = (k1 < HS) ? W_mu [cc * ZH * HS + n * HS + k1] : 0.0f;
        float s0 = (k0 < HS) ? W_sig[cc * ZH * HS + n * HS + k0] : 0.0f;
        float s1 = (k1 < HS) ? W_sig[cc * ZH * HS + n * HS + k1] : 0.0f;
        unsigned h, l;
        split2(m0, m1, h, l);
        gW[cc][GW12 + W1Hr + idx] = h;
        gW[cc][GW12 + W1Lr + idx] = l;
        split2(s0, s1, h, l);
        gW[cc][GW12 + W2Hr + idx] = h;
        gW[cc][GW12 + W2Lr + idx] = l;
    }
    if (tid < 64) {
        gBB[cc][tid]       = (tid < HS) ? b_in[cc * HS + tid] : 0.0f;
        gBB[cc][64 + tid]  = b_mu [cc * ZH + tid];
        gBB[cc][128 + tid] = b_sig[cc * ZH + tid];
    }
}

// ---------------- main kernel ----------------
__global__ void __launch_bounds__(TPB, 2)
flow_kernel(const float* __restrict__ mean,  const float* __restrict__ logvar,
            const float* __restrict__ eps,
            float* __restrict__ out, int Brows)
{
    extern __shared__ float sm[];
    unsigned* uW0  = (unsigned*)(sm + OW0);
    unsigned* uW12 = (unsigned*)(sm + OW12);
    float*    sZ1  = sm + OZ1;
    float*    sZ2  = sm + OZ2;
    unsigned* uHH  = (unsigned*)(sm + OHH);
    unsigned* uHL  = (unsigned*)(sm + OHL);
    float*    sQ0  = sm + OQ0;
    float*    sLD  = sm + OLD;
    float*    sSS  = sm + OSS;

    const int tid  = threadIdx.x;
    const int lane = tid & 31;
    const int wid  = tid >> 5;
    const int wm   = wid & 1;          // m-group: rows 32*wm..+31
    const int wn   = wid >> 1;         // n-quarter (0..3)
    const int gid  = lane >> 2;
    const int tig  = lane & 3;
    const int rb   = 32 * wm;
    const int rowBase = blockIdx.x * MR;

    // ---- prefetch coupling 0: group A = {W0,b}, group B = {W12} ----
    {
        const float4* s0 = (const float4*)(&gW[0][0]);
        float4* d0 = (float4*)(sm + OW0);
        for (int i = tid; i < 4032 / 4; i += TPB) cp16(d0 + i, s0 + i);
        if (tid < 48) cp16((float4*)(sm + OB) + tid, (const float4*)(&gBB[0][0]) + tid);
        CP_COMMIT();
        const float4* s1 = (const float4*)(&gW[0][GW12]);
        float4* d1 = (float4*)(sm + OW12);
        for (int i = tid; i < 9216 / 4; i += TPB) cp16(d1 + i, s1 + i);
        CP_COMMIT();
    }

    // ---- zero H k-pad (kp 28..31, 64 rows) ----
    if (tid < 256) {
        int r = tid >> 2, kp = 28 + (tid & 3);
        uHH[r * KPI + kp] = 0u;
        uHL[r * KPI + kp] = 0u;
    }

    // ================= reparam (4 threads/row) =================
    {
        const int rrow = tid >> 2, p = tid & 3;
        float part = 0.0f;
#pragma unroll
        for (int j = 0; j < 8; j++) {
            int q = p + 4 * j;
            size_t g = (size_t)(rowBase + rrow) * 32 + q;
            float4 mv = ((const float4*)mean  )[g];
            float4 lv = ((const float4*)logvar)[g];
            float4 ev = ((const float4*)eps   )[g];
            float4 z4;
            z4.x = fmaf(ev.x, __expf(0.5f * lv.x), mv.x);
            z4.y = fmaf(ev.y, __expf(0.5f * lv.y), mv.y);
            z4.z = fmaf(ev.z, __expf(0.5f * lv.z), mv.z);
            z4.w = fmaf(ev.w, __expf(0.5f * lv.w), mv.w);
            part += lv.x + lv.y + lv.z + lv.w;
            part = fmaf(ev.x, ev.x, part);
            part = fmaf(ev.y, ev.y, part);
            part = fmaf(ev.z, ev.z, part);
            part = fmaf(ev.w, ev.w, part);
            if (q < 16)
                *(float4*)&sZ1[rrow * PZ + 4 * q] = z4;
            else
                *(float4*)&sZ2[rrow * PZ + 4 * (q - 16)] = z4;
        }
        part += __shfl_xor_sync(0xffffffffu, part, 1);
        part += __shfl_xor_sync(0xffffffffu, part, 2);
        if (p == 0) sQ0[rrow] = -0.5f * part;
    }

    float ldp[4] = {0.f, 0.f, 0.f, 0.f};
    float ssp[4] = {0.f, 0.f, 0.f, 0.f};

    // ================= couplings =================
#pragma unroll 1
    for (int cc = 0; cc < NC; cc++) {
        // wait group A of cc ({W0,b}); group B ({W12}) may still stream
        CP_WAIT1();
        __syncthreads();

        const float* sB0 = sm + OB + 192 * (cc & 1);
        const float* sB1 = sB0 + 64;
        const float* sB2 = sB0 + 128;
        const float* sZa = (cc & 1) ? sZ2 : sZ1;
        float*       sZu = (cc & 1) ? sZ1 : sZ2;

        // ---- GEMM1: H = tanh(Za @ W0^T + b0); m32 x n16 (wn3: n8) ----
        {
            const int NT = (wn < 3) ? 2 : 1;   // 7 n-tiles over 4 quarters
            float acc[2][2][4] = {};
#pragma unroll
            for (int c = 0; c < 4; c++) {
                unsigned ah[2][4], al[2][4];
#pragma unroll
                for (int s2 = 0; s2 < 2; s2++) {
                    int ra0 = rb + 16 * s2 + gid, ra1 = ra0 + 8;
                    float2 v00 = ((const float2*)&sZa[ra0 * PZ])[tig +     8 * c];
                    float2 v10 = ((const float2*)&sZa[ra1 * PZ])[tig +     8 * c];
                    float2 v01 = ((const float2*)&sZa[ra0 * PZ])[tig + 4 + 8 * c];
                    float2 v11 = ((const float2*)&sZa[ra1 * PZ])[tig + 4 + 8 * c];
                    split2(v00.x, v00.y, ah[s2][0], al[s2][0]);
                    split2(v10.x, v10.y, ah[s2][1], al[s2][1]);
                    split2(v01.x, v01.y, ah[s2][2], al[s2][2]);
                    split2(v11.x, v11.y, ah[s2][3], al[s2][3]);
                }
#pragma unroll
                for (int nn = 0; nn < 2; nn++) {
                    if (nn >= NT) break;
                    int nrow = 8 * (2 * wn + nn) + gid;
                    unsigned bh0 = uW0[W0H + nrow * KPI + tig +     8 * c];
                    unsigned bh1 = uW0[W0H + nrow * KPI + tig + 4 + 8 * c];
                    unsigned bl0 = uW0[W0L + nrow * KPI + tig +     8 * c];
                    unsigned bl1 = uW0[W0L + nrow * KPI + tig + 4 + 8 * c];
#pragma unroll
                    for (int s2 = 0; s2 < 2; s2++) {
                        mma16(acc[s2][nn], ah[s2], bh0, bh1);
                        mma16(acc[s2][nn], ah[s2], bl0, bl1);
                        mma16(acc[s2][nn], al[s2], bh0, bh1);
                    }
                }
            }
            // epilogue: bias + tanh, write H pre-split/packed
#pragma unroll
            for (int nn = 0; nn < 2; nn++) {
                if (nn >= NT) break;
                int nt  = 2 * wn + nn;
                int col = 8 * nt + 2 * tig;
                int kp  = 4 * nt + tig;
                float bb0 = sB0[col], bb1 = sB0[col + 1];
#pragma unroll
                for (int s2 = 0; s2 < 2; s2++) {
                    int ra0 = rb + 16 * s2 + gid, ra1 = ra0 + 8;
                    float t00 = tanh_fast(acc[s2][nn][0] + bb0);
                    float t01 = tanh_fast(acc[s2][nn][1] + bb1);
                    float t10 = tanh_fast(acc[s2][nn][2] + bb0);
                    float t11 = tanh_fast(acc[s2][nn][3] + bb1);
                    unsigned h, l;
                    split2(t00, t01, h, l);
                    uHH[ra0 * KPI + kp] = h;
                    uHL[ra0 * KPI + kp] = l;
                    split2(t10, t11, h, l);
                    uHH[ra1 * KPI + kp] = h;
                    uHL[ra1 * KPI + kp] = l;
                }
            }
        }
        CP_WAIT0();                    // W12(cc) landed
        __syncthreads();               // H visible; W0(cc) reads done

        // ---- prefetch {W0,b}(cc+1) (overlaps GEMM2; W0 buffer now free) ----
        if (cc < 3) {
            const float4* s0 = (const float4*)(&gW[cc + 1][0]);
            float4* d0 = (float4*)(sm + OW0);
            for (int i = tid; i < 4032 / 4; i += TPB) cp16(d0 + i, s0 + i);
            if (tid < 48)
                cp16((float4*)(sm + OB + 192 * ((cc + 1) & 1)) + tid,
                     (const float4*)(&gBB[cc + 1][0]) + tid);
            CP_COMMIT();
        }

        // ---- GEMM2: mu/sig heads; m32 x n16 (2 tiles), K=64 ----
        {
            float am [2][2][4] = {};
            float as2[2][2][4] = {};
#pragma unroll
            for (int c = 0; c < 4; c++) {
                unsigned ah[2][4], al[2][4];
#pragma unroll
                for (int s2 = 0; s2 < 2; s2++) {
                    int ra0 = rb + 16 * s2 + gid, ra1 = ra0 + 8;
                    ah[s2][0] = uHH[ra0 * KPI + tig +     8 * c];
                    ah[s2][1] = uHH[ra1 * KPI + tig +     8 * c];
                    ah[s2][2] = uHH[ra0 * KPI + tig + 4 + 8 * c];
                    ah[s2][3] = uHH[ra1 * KPI + tig + 4 + 8 * c];
                    al[s2][0] = uHL[ra0 * KPI + tig +     8 * c];
                    al[s2][1] = uHL[ra1 * KPI + tig +     8 * c];
                    al[s2][2] = uHL[ra0 * KPI + tig + 4 + 8 * c];
                    al[s2][3] = uHL[ra1 * KPI + tig + 4 + 8 * c];
                }
#pragma unroll
                for (int nn = 0; nn < 2; nn++) {
                    int nrow = 8 * (2 * wn + nn) + gid;
                    unsigned bh0 = uW12[W1Hr + nrow * KPI + tig +     8 * c];
                    unsigned bh1 = uW12[W1Hr + nrow * KPI + tig + 4 + 8 * c];
                    unsigned bl0 = uW12[W1Lr + nrow * KPI + tig +     8 * c];
                    unsigned bl1 = uW12[W1Lr + nrow * KPI + tig + 4 + 8 * c];
#pragma unroll
                    for (int s2 = 0; s2 < 2; s2++) {
                        mma16(am[s2][nn], ah[s2], bh0, bh1);
                        mma16(am[s2][nn], ah[s2], bl0, bl1);
                        mma16(am[s2][nn], al[s2], bh0, bh1);
                    }
                    bh0 = uW12[W2Hr + nrow * KPI + tig +     8 * c];
                    bh1 = uW12[W2Hr + nrow * KPI + tig + 4 + 8 * c];
                    bl0 = uW12[W2Lr + nrow * KPI + tig +     8 * c];
                    bl1 = uW12[W2Lr + nrow * KPI + tig + 4 + 8 * c];
#pragma unroll
                    for (int s2 = 0; s2 < 2; s2++) {
                        mma16(as2[s2][nn], ah[s2], bh0, bh1);
                        mma16(as2[s2][nn], ah[s2], bl0, bl1);
                        mma16(as2[s2][nn], al[s2], bh0, bh1);
                    }
                }
            }
            // ---- epilogue: sig, z update, logdet ----
            const bool fin = (cc >= 2);
#pragma unroll
            for (int s2 = 0; s2 < 2; s2++) {
                int ra0 = rb + 16 * s2 + gid, ra1 = ra0 + 8;
#pragma unroll
                for (int nn = 0; nn < 2; nn++) {
                    int col = 8 * (2 * wn + nn) + 2 * tig;
#pragma unroll
                    for (int d = 0; d < 2; d++) {
                        float bm = sB1[col + d];
                        float bs = sB2[col + d];
                        {
                            float mu = am[s2][nn][d] + bm;
                            float x  = as2[s2][nn][d] + bs;
                            float sg = fmaf(tanh_fast(0.5f * x), 0.5f, 0.5f);
                            ldp[2 * s2] += __logf(sg);
                            float zn = fmaf(sZu[ra0 * PZ + col + d], sg, mu);
                            sZu[ra0 * PZ + col + d] = zn;
                            if (fin) ssp[2 * s2] = fmaf(zn, zn, ssp[2 * s2]);
                        }
                        {
                            float mu = am[s2][nn][d + 2] + bm;
                            float x  = as2[s2][nn][d + 2] + bs;
                            float sg = fmaf(tanh_fast(0.5f * x), 0.5f, 0.5f);
                            ldp[2 * s2 + 1] += __logf(sg);
                            float zn = fmaf(sZu[ra1 * PZ + col + d], sg, mu);
                            sZu[ra1 * PZ + col + d] = zn;
                            if (fin) ssp[2 * s2 + 1] = fmaf(zn, zn, ssp[2 * s2 + 1]);
                        }
                    }
                }
            }
        }
        __syncthreads();               // z updated; W12(cc) reads done

        // ---- prefetch {W12}(cc+1) (overlaps next GEMM1) ----
        if (cc < 3) {
            const float4* s1 = (const float4*)(&gW[cc + 1][GW12]);
            float4* d1 = (float4*)(sm + OW12);
            for (int i = tid; i < 9216 / 4; i += TPB) cp16(d1 + i, s1 + i);
            CP_COMMIT();
        }
    }

    // ================= write z (coalesced float4) =================
#pragma unroll
    for (int i = 0; i < 8; i++) {
        int idx = tid + TPB * i;            // 0..2047
        int row = idx >> 5, q = idx & 31;
        float4 v = (q < 16)
            ? *(const float4*)&sZ1[row * PZ + 4 * q]
            : *(const float4*)&sZ2[row * PZ + 4 * (q - 16)];
        ((float4*)out)[(size_t)(rowBase + row) * 32 + q] = v;
    }

    // ================= densities =================
#pragma unroll
    for (int s = 0; s < 4; s++) {
        float l = ldp[s], v = ssp[s];
        l += __shfl_xor_sync(0xffffffffu, l, 1);
        l += __shfl_xor_sync(0xffffffffu, l, 2);
        v += __shfl_xor_sync(0xffffffffu, v, 1);
        v += __shfl_xor_sync(0xffffffffu, v, 2);
        if (tig == 0) {
            int row = rb + 16 * (s >> 1) + 8 * (s & 1) + gid;
            sLD[wn * 64 + row] = l;
            sSS[wn * 64 + row] = v;
        }
    }
    __syncthreads();
    if (tid < 64) {
        float l = sLD[tid] + sLD[64 + tid] + sLD[128 + tid] + sLD[192 + tid];
        float s = sSS[tid] + sSS[64 + tid] + sSS[128 + tid] + sSS[192 + tid];
        size_t base = (size_t)Brows * ZZ;
        out[base + rowBase + tid]         = -0.5f * s;
        out[base + Brows + rowBase + tid] = sQ0[tid] - l;
    }
}

extern "C" void kernel_launch(void* const* d_in, const int* in_sizes, int n_in,
                              void* d_out, int out_size)
{
    const float* mean   = (const float*)d_in[0];
    const float* logvar = (const float*)d_in[1];
    const float* eps    = (const float*)d_in[2];
    const float* W_in   = (const float*)d_in[3];
    const float* b_in   = (const float*)d_in[4];
    const float* W_mu   = (const float*)d_in[5];
    const float* b_mu   = (const float*)d_in[6];
    const float* W_sig  = (const float*)d_in[7];
    const float* b_sig  = (const float*)d_in[8];
    float* out = (float*)d_out;

    int Brows = in_sizes[0] / ZZ;

    cudaFuncSetAttribute(flow_kernel, cudaFuncAttributeMaxDynamicSharedMemorySize, SMEM_BYTES);

    presplit_kernel<<<NC, 256>>>(W_in, b_in, W_mu, b_mu, W_sig, b_sig);
    flow_kernel<<<Brows / MR, TPB, SMEM_BYTES>>>(mean, logvar, eps, out, Brows);
}